// round 7
// baseline (speedup 1.0000x reference)
#include <cuda_runtime.h>
#include <math.h>

#define BSZ   65536
#define SEQ   25
#define HID   64
#define ACT   4
#define TSTEP 16
#define BETA  0.95f
#define THRV  1.0f
#define ELIG_DECAY 0.95f
#define ELIG_C     (-0.002f)    // A_PLUS - A_MINUS

#define NBLK  148               // 1 block per SM, single wave
#define WPB   32                // warps per block (1024 threads)
// 65536 = 4736*13 + 3968 -> first 3968 warps take 14 rows (<= nibble cap 15)
#define ROWS_EXTRA 3968

#define W3_SCALE     8388608.0f          // 2^23 (exact integer reduction)
#define W3_INV_SCALE (1.0f / 8388608.0f)

// ---- aligned-region byte offsets (from 16KB-aligned base "ab") ----
// tbl6 : 10 groups x 64 pat x 32 lanes x float2   = 163840 (group g at g*16384)
// tbl4 : 16 pat x 32 lanes x float2               =   4096 (at 163840, 16K-aligned)
// tbl3 : 8 groups x 256 pat x 4 actions x int32   =  32768 (at 167936)
// w1t  : 25 x 32 x float2                         =   6400 (at 200704)
// flag : 4                                          (at 207104)
// s2sh/s3sh (24KB) alias tbl6 region after the main loop.
#define OFF_TBL4  163840
#define OFF_TBL3  167936
#define OFF_W1T   200704
#define OFF_FLAG  207104
#define SMEM_REQ  (207232 + 16384)   // payload + alignment slack

// Graph-safe persistent scratch; last block re-zeroes everything each call.
__device__ float    g_s2sum[TSTEP * HID];
__device__ float    g_s3sum[TSTEP * ACT];
__device__ unsigned g_ctr;

__device__ __forceinline__ int redux_add_grp(int v, unsigned mask) {
    int r;
    asm volatile("redux.sync.add.s32 %0, %1, %2;" : "=r"(r) : "r"(v), "r"(mask));
    return r;
}

// W2 LUT lookup: v has the pattern pre-shifted to bits [8,14).
// addr = (v & MASK) | tb_lane  (single LOP3, valid because tb_lane bits[13:8]=0)
template <int IMM, unsigned MASK>
__device__ __forceinline__ void lutW2(unsigned v, unsigned tb_lane,
                                      unsigned long long& acc) {
    unsigned addr;
    asm("lop3.b32 %0, %1, %2, %3, 0xEA;"
        : "=r"(addr) : "r"(v), "n"(MASK), "r"(tb_lane));
    unsigned long long w;
    asm volatile("ld.shared.b64 %0, [%1+%2];" : "=l"(w) : "r"(addr), "n"(IMM));
    asm("add.rn.f32x2 %0, %0, %1;" : "+l"(acc) : "l"(w));
}

// ---------------------------------------------------------------------------
// Fused kernel. One warp per batch row (13-14 rows/warp).
// Lane l owns hidden neurons l and l+32 (layers 1, 2).
// Layer 3: 8-bit integer LUT + one 8-lane subset redux; lane l owns action l&3.
// ---------------------------------------------------------------------------
__global__ void __launch_bounds__(1024, 1) snn_main(
    const float* __restrict__ x,   // [B, 25]
    const float* __restrict__ W1,  // [64, 25]
    const float* __restrict__ b1,  // [64]
    const float* __restrict__ W2,  // [64, 64]
    const float* __restrict__ b2,  // [64]
    const float* __restrict__ W3,  // [4, 64]
    const float* __restrict__ b3,  // [4]
    const float* __restrict__ elig0,
    float* __restrict__ out, int elig_off)
{
    extern __shared__ unsigned char smem_raw[];
    const unsigned dyn = (unsigned)__cvta_generic_to_shared(smem_raw);
    const unsigned ab  = (dyn + 16383u) & 0xFFFFC000u;   // 16KB-aligned base
    unsigned char* base = smem_raw + (ab - dyn);

    const int tid  = threadIdx.x;
    const int lane = tid & 31;
    const int warp = tid >> 5;

    // ---- build 6-bit W2 LUT (tbl6[g][pat][lane] = float2 partial col sums) ----
    if (tid < 320) {
        const int g = tid >> 5, l = tid & 31;
        float wa[6], wb[6];
        #pragma unroll
        for (int b = 0; b < 6; b++) {
            int j = 6 * g + b;
            wa[b] = W2[l * HID + j];
            wb[b] = W2[(l + 32) * HID + j];
        }
        float2* tg = (float2*)(base + g * 16384) + l;     // stride 32 float2
        tg[0] = make_float2(0.f, 0.f);
        for (int n = 1; n < 64; n++) {
            int b = __ffs(n) - 1;
            float2 prev = tg[(n & (n - 1)) * 32];
            tg[n * 32] = make_float2(prev.x + wa[b], prev.y + wb[b]);
        }
    } else if (tid < 352) {
        const int l = tid - 320;
        float wa[4], wb[4];
        #pragma unroll
        for (int b = 0; b < 4; b++) {
            int j = 60 + b;
            wa[b] = W2[l * HID + j];
            wb[b] = W2[(l + 32) * HID + j];
        }
        float2* tg = (float2*)(base + OFF_TBL4) + l;
        tg[0] = make_float2(0.f, 0.f);
        for (int n = 1; n < 16; n++) {
            int b = __ffs(n) - 1;
            float2 prev = tg[(n & (n - 1)) * 32];
            tg[n * 32] = make_float2(prev.x + wa[b], prev.y + wb[b]);
        }
    }
    // ---- build 8-bit integer W3 LUT: tbl3[g][pat][a] ----
    for (int pair = tid; pair < 2048; pair += 1024) {
        int g = pair >> 8, pat = pair & 255;
        int s0 = 0, s1 = 0, s2v = 0, s3v = 0;
        #pragma unroll
        for (int b = 0; b < 8; b++) {
            if (pat & (1 << b)) {
                int j = 8 * g + b;
                s0 += __float2int_rn(W3[0 * HID + j] * W3_SCALE);
                s1 += __float2int_rn(W3[1 * HID + j] * W3_SCALE);
                s2v += __float2int_rn(W3[2 * HID + j] * W3_SCALE);
                s3v += __float2int_rn(W3[3 * HID + j] * W3_SCALE);
            }
        }
        int* dst = (int*)(base + OFF_TBL3 + g * 4096 + pat * 16);
        dst[0] = s0; dst[1] = s1; dst[2] = s2v; dst[3] = s3v;
    }
    // ---- stage W1 transposed ----
    {
        float2* w1t = (float2*)(base + OFF_W1T);
        for (int idx = tid; idx < SEQ * 32; idx += 1024) {
            int k = idx >> 5, l = idx & 31;
            w1t[k * 32 + l] =
                make_float2(W1[l * SEQ + k], W1[(l + 32) * SEQ + k]);
        }
    }
    __syncthreads();

    // per-lane constants
    const float b1_0 = b1[lane], b1_1 = b1[lane + 32];
    const float b2_0 = b2[lane], b2_1 = b2[lane + 32];
    const int   g3 = lane >> 2, a3 = lane & 3;
    const float b3me = b3[a3];
    const unsigned prmt_sel = 0x4440u | (unsigned)(g3 & 3);
    const bool use_hi = g3 >= 4;
    const unsigned grpmask = 0x11111111u << a3;
    const unsigned base3_lane = ab + OFF_TBL3 + (unsigned)g3 * 4096u
                                             + (unsigned)a3 * 4u;
    const unsigned tb_lane = ab + (unsigned)lane * 8u;  // bits [13:8] = 0

    unsigned long long b2p;
    asm("mov.b64 %0, {%1, %2};" : "=l"(b2p) : "f"(b2_0), "f"(b2_1));

    const int lmod = lane & 15;
    const int lhi  = lane >> 4;

    // spike counters (register-resident; max 14 per nibble)
    unsigned c00 = 0u, c01 = 0u;   // neuron l: t 0-7, t 8-15
    unsigned c10 = 0u, c11 = 0u;   // neuron l+32
    unsigned cA = 0u, cB = 0u;     // s3 at (t=lmod, a=lhi) and (t=lmod, a=2+lhi)

    const int gwarp = blockIdx.x * WPB + warp;
    const int row0  = gwarp * 13 + min(gwarp, ROWS_EXTRA);
    const int nrows = 13 + (gwarp < ROWS_EXTRA ? 1 : 0);

    const float2* w1t = (const float2*)(base + OFF_W1T);

    for (int r = 0; r < nrows; r++) {
        const int row = row0 + r;

        // ---- cur1 = x[row] @ W1^T + b1 (coalesced + shfl broadcast) ----
        const float* xr = x + row * SEQ;
        float xown = (lane < SEQ) ? xr[lane] : 0.0f;
        float cur0 = b1_0, cur1v = b1_1;
        #pragma unroll
        for (int k = 0; k < SEQ; k++) {
            float xv = __shfl_sync(0xffffffffu, xown, k);
            float2 w = w1t[k * 32 + lane];
            cur0  = fmaf(xv, w.x, cur0);
            cur1v = fmaf(xv, w.y, cur1v);
        }

        float m1_0 = 0.f, m1_1 = 0.f, m2_0 = 0.f, m2_1 = 0.f;
        float m3me = 0.f, acme = 0.f;

        #pragma unroll
        for (int t = 0; t < TSTEP; t++) {
            // ---- layer 1 ----
            m1_0 = fmaf(BETA, m1_0, cur0);
            m1_1 = fmaf(BETA, m1_1, cur1v);
            bool f0 = m1_0 > THRV, f1 = m1_1 > THRV;
            if (f0) m1_0 -= THRV;
            if (f1) m1_1 -= THRV;
            unsigned ma = __ballot_sync(0xffffffffu, f0);  // neurons 0..31
            unsigned mb = __ballot_sync(0xffffffffu, f1);  // neurons 32..63

            // ---- layer 2: 11 LUT lookups (1 SHF + 1 LOP3 + LDS + FADD2 each) ----
            unsigned long long a01 = b2p, aA = 0, aB = 0, aC = 0;
            lutW2<0 * 16384, 0x3F00u>(ma << 8,                      tb_lane, a01);
            lutW2<1 * 16384, 0x3F00u>(ma << 2,                      tb_lane, aA);
            lutW2<2 * 16384, 0x3F00u>(ma >> 4,                      tb_lane, aB);
            lutW2<3 * 16384, 0x3F00u>(ma >> 10,                     tb_lane, aC);
            lutW2<4 * 16384, 0x3F00u>(ma >> 16,                     tb_lane, a01);
            lutW2<5 * 16384, 0x3F00u>(__funnelshift_r(ma, mb, 22),  tb_lane, aA);
            lutW2<6 * 16384, 0x3F00u>(mb << 4,                      tb_lane, aB);
            lutW2<7 * 16384, 0x3F00u>(mb >> 2,                      tb_lane, aC);
            lutW2<8 * 16384, 0x3F00u>(mb >> 8,                      tb_lane, a01);
            lutW2<9 * 16384, 0x3F00u>(mb >> 14,                     tb_lane, aA);
            lutW2<OFF_TBL4,  0x0F00u>(mb >> 20,                     tb_lane, aB);
            asm("add.rn.f32x2 %0, %0, %1;" : "+l"(a01) : "l"(aA));
            asm("add.rn.f32x2 %0, %0, %1;" : "+l"(aB)  : "l"(aC));
            asm("add.rn.f32x2 %0, %0, %1;" : "+l"(a01) : "l"(aB));
            float a0, a1;
            asm("mov.b64 {%0, %1}, %2;" : "=f"(a0), "=f"(a1) : "l"(a01));

            m2_0 = fmaf(BETA, m2_0, a0);
            m2_1 = fmaf(BETA, m2_1, a1);
            bool q0 = m2_0 > THRV, q1 = m2_1 > THRV;
            if (q0) m2_0 -= THRV;
            if (q1) m2_1 -= THRV;

            // s2 nibble counters (t immediate under full unroll)
            unsigned nib = 1u << ((t & 7) * 4);
            if (t < 8) { c00 += q0 ? nib : 0u; c10 += q1 ? nib : 0u; }
            else       { c01 += q0 ? nib : 0u; c11 += q1 ? nib : 0u; }

            // ---- layer 3: 8-bit int LUT + one subset redux ----
            unsigned mq_lo = __ballot_sync(0xffffffffu, q0);  // s2 neurons 0..31
            unsigned mq_hi = __ballot_sync(0xffffffffu, q1);  // s2 neurons 32..63
            unsigned src = use_hi ? mq_hi : mq_lo;
            unsigned pat = __byte_perm(src, 0u, prmt_sel);    // byte g3 of mask
            unsigned addr3 = base3_lane + (pat << 4);
            int part;
            asm volatile("ld.shared.b32 %0, [%1];" : "=r"(part) : "r"(addr3));
            int tot = redux_add_grp(part, grpmask);           // exact s32 sum

            float pf = fmaf((float)tot, W3_INV_SCALE, b3me);
            m3me = fmaf(BETA, m3me, pf);
            bool gme = m3me > THRV;
            if (gme) { m3me -= THRV; acme += 1.0f; }

            unsigned bal = __ballot_sync(0xffffffffu, gme);   // bits repeat mod 4
            if (lmod == t) {
                cA += (bal >> lhi) & 1u;
                cB += (bal >> (2 + lhi)) & 1u;
            }
        }

        // ---- softmax(acc / T): gather 4 actions, lane 0 writes ----
        float gg0 = __shfl_sync(0xffffffffu, acme, 0);
        float gg1 = __shfl_sync(0xffffffffu, acme, 1);
        float gg2 = __shfl_sync(0xffffffffu, acme, 2);
        float gg3 = __shfl_sync(0xffffffffu, acme, 3);
        if (lane == 0) {
            const float invT = 1.0f / (float)TSTEP;
            float r0 = gg0 * invT, r1 = gg1 * invT;
            float r2 = gg2 * invT, r3 = gg3 * invT;
            float mx = fmaxf(fmaxf(r0, r1), fmaxf(r2, r3));
            float e0 = __expf(r0 - mx), e1 = __expf(r1 - mx);
            float e2 = __expf(r2 - mx), e3 = __expf(r3 - mx);
            float rs = __fdividef(1.0f, e0 + e1 + e2 + e3);
            float4 o = make_float4(e0 * rs, e1 * rs, e2 * rs, e3 * rs);
            *reinterpret_cast<float4*>(out + (size_t)row * ACT) = o;
        }
    }

    // ---- flush spike counters (alias counter buffers onto tbl6 region) ----
    __syncthreads();                       // all warps done with the LUTs
    unsigned (*s2sh)[32][4] = (unsigned(*)[32][4])(base);          // 16KB
    unsigned (*s3sh)[32][2] = (unsigned(*)[32][2])(base + 16384);  //  8KB
    s2sh[warp][lane][0] = c00;
    s2sh[warp][lane][1] = c01;
    s2sh[warp][lane][2] = c10;
    s2sh[warp][lane][3] = c11;
    s3sh[warp][lane][0] = cA;
    s3sh[warp][lane][1] = cB;
    __syncthreads();

    {   // 1024 (t, neuron) cells, one per thread
        int p = tid;
        int t = p >> 6, j = p & 63;
        int ln = j & 31, half = j >> 5;
        int wsel = half * 2 + (t >> 3);
        int sh = (t & 7) * 4;
        unsigned c = 0;
        #pragma unroll
        for (int w = 0; w < WPB; w++)
            c += (s2sh[w][ln][wsel] >> sh) & 15u;
        atomicAdd(&g_s2sum[p], (float)c);
    }
    if (tid < TSTEP * ACT) {
        int t = tid >> 2, a = tid & 3;
        int ln = t + ((a & 1) << 4);
        int s = a >> 1;
        unsigned c = 0;
        #pragma unroll
        for (int w = 0; w < WPB; w++)
            c += s3sh[w][ln][s];
        atomicAdd(&g_s3sum[tid], (float)c);
    }

    // ---- last-block: eligibility trace + reset of globals ----
    unsigned* flagp = (unsigned*)(base + OFF_FLAG);
    __threadfence();
    __syncthreads();
    if (tid == 0)
        *flagp = (atomicAdd(&g_ctr, 1u) == (unsigned)(NBLK - 1)) ? 1u : 0u;
    __syncthreads();
    if (*flagp) {
        if (tid < ACT * HID) {
            int a = tid >> 6, h = tid & 63;
            const float invB = 1.0f / (float)BSZ;
            volatile float* s3v = g_s3sum;
            volatile float* s2v = g_s2sum;
            float e = elig0[tid];
            #pragma unroll
            for (int t = 0; t < TSTEP; t++) {
                float post = s3v[t * ACT + a] * invB;
                float pre  = s2v[t * HID + h] * invB;
                e = ELIG_DECAY * e + ELIG_C * (post * pre);
            }
            out[elig_off + tid] = e;
        }
        __syncthreads();
        if (tid < TSTEP * HID) g_s2sum[tid] = 0.0f;
        if (tid < TSTEP * ACT) g_s3sum[tid] = 0.0f;
        if (tid == 0) g_ctr = 0u;
    }
}

// ---------------------------------------------------------------------------
// Inputs (metadata order): x, W1, b1, W2, b2, W3, b3, elig0
// Output: probs [B,4] then elig [4,64] at the tail of out.
// ---------------------------------------------------------------------------
extern "C" void kernel_launch(void* const* d_in, const int* in_sizes, int n_in,
                              void* d_out, int out_size) {
    const float* x     = (const float*)d_in[0];
    const float* W1    = (const float*)d_in[1];
    const float* b1    = (const float*)d_in[2];
    const float* W2    = (const float*)d_in[3];
    const float* b2    = (const float*)d_in[4];
    const float* W3    = (const float*)d_in[5];
    const float* b3    = (const float*)d_in[6];
    const float* elig0 = (const float*)d_in[7];
    float* out = (float*)d_out;

    cudaFuncSetAttribute(snn_main, cudaFuncAttributeMaxDynamicSharedMemorySize,
                         SMEM_REQ);
    int elig_off = out_size - ACT * HID;
    snn_main<<<NBLK, 1024, SMEM_REQ>>>(x, W1, b1, W2, b2, W3, b3,
                                       elig0, out, elig_off);
}

// round 9
// speedup vs baseline: 1.1521x; 1.1521x over previous
#include <cuda_runtime.h>
#include <math.h>

#define BSZ   65536
#define SEQ   25
#define HID   64
#define ACT   4
#define TSTEP 16
#define BETA  0.95f
#define THRV  1.0f
#define ELIG_DECAY 0.95f
#define ELIG_C     (-0.002f)    // A_PLUS - A_MINUS

#define NBLK  148               // 1 block per SM, single wave
#define WPB   32                // warps per block (1024 threads)
// 65536 = 4736*13 + 3968 -> first 3968 warps take 14 rows (<= nibble cap 15)
#define ROWS_EXTRA 3968

#define W3_SCALE     8388608.0f          // 2^23 (exact integer reduction)
#define W3_INV_SCALE (1.0f / 8388608.0f)

// ---- aligned-region byte offsets (from 16KB-aligned base "ab") ----
// tbl6 : 10 groups x 64 pat x 32 lanes x float2 = 163840 (group g at g*16384)
// tbl4 : 16 pat x 32 lanes x float2             =   4096 (at 163840, 16K-aligned)
// w1t  : 25 x 32 x float2                       =   6400 (at 167936)
// flag : 4                                        (at 174336)
// s2sh/s3sh (24KB) alias tbl6 region after the main loop.
#define OFF_TBL4  163840
#define OFF_W1T   167936
#define OFF_FLAG  174336
#define SMEM_REQ  (174464 + 16384)   // payload + alignment slack

// Graph-safe persistent scratch; last block re-zeroes everything each call.
__device__ float    g_s2sum[TSTEP * HID];
__device__ float    g_s3sum[TSTEP * ACT];
__device__ unsigned g_ctr;

__device__ __forceinline__ int warp_redux_add_s32(int v) {
    int r;
    asm volatile("redux.sync.add.s32 %0, %1, 0xffffffff;" : "=r"(r) : "r"(v));
    return r;
}

// W2 LUT lookup: v has the pattern pre-shifted to bits [8,14).
// addr = (v & MASK) | tb_lane  (single LOP3, valid because tb_lane bits[13:8]=0)
template <int IMM, unsigned MASK>
__device__ __forceinline__ void lutW2(unsigned v, unsigned tb_lane,
                                      unsigned long long& acc) {
    unsigned addr;
    asm("lop3.b32 %0, %1, %2, %3, 0xEA;"
        : "=r"(addr) : "r"(v), "n"(MASK), "r"(tb_lane));
    unsigned long long w;
    asm volatile("ld.shared.b64 %0, [%1+%2];" : "=l"(w) : "r"(addr), "n"(IMM));
    asm("add.rn.f32x2 %0, %0, %1;" : "+l"(acc) : "l"(w));
}

// ---------------------------------------------------------------------------
// Fused kernel. One warp per batch row (13-14 rows/warp).
// Lane l owns hidden neurons l and l+32 (layers 1, 2).
// Layer 3: exact integer IMAD partials (FMA pipe) + 4 warp reduxes;
// lane l keeps m3/acc for action lane&3.
// ---------------------------------------------------------------------------
__global__ void __launch_bounds__(1024, 1) snn_main(
    const float* __restrict__ x,   // [B, 25]
    const float* __restrict__ W1,  // [64, 25]
    const float* __restrict__ b1,  // [64]
    const float* __restrict__ W2,  // [64, 64]
    const float* __restrict__ b2,  // [64]
    const float* __restrict__ W3,  // [4, 64]
    const float* __restrict__ b3,  // [4]
    const float* __restrict__ elig0,
    float* __restrict__ out, int elig_off)
{
    extern __shared__ unsigned char smem_raw[];
    const unsigned dyn = (unsigned)__cvta_generic_to_shared(smem_raw);
    const unsigned ab  = (dyn + 16383u) & 0xFFFFC000u;   // 16KB-aligned base
    unsigned char* base = smem_raw + (ab - dyn);

    const int tid  = threadIdx.x;
    const int lane = tid & 31;
    const int warp = tid >> 5;

    // ---- build 6-bit W2 LUT (tbl6[g][pat][lane] = float2 partial col sums) ----
    if (tid < 320) {
        const int g = tid >> 5, l = tid & 31;
        float wa[6], wb[6];
        #pragma unroll
        for (int b = 0; b < 6; b++) {
            int j = 6 * g + b;
            wa[b] = W2[l * HID + j];
            wb[b] = W2[(l + 32) * HID + j];
        }
        float2* tg = (float2*)(base + g * 16384) + l;     // stride 32 float2
        tg[0] = make_float2(0.f, 0.f);
        for (int n = 1; n < 64; n++) {
            int b = __ffs(n) - 1;
            float2 prev = tg[(n & (n - 1)) * 32];
            tg[n * 32] = make_float2(prev.x + wa[b], prev.y + wb[b]);
        }
    } else if (tid < 352) {
        const int l = tid - 320;
        float wa[4], wb[4];
        #pragma unroll
        for (int b = 0; b < 4; b++) {
            int j = 60 + b;
            wa[b] = W2[l * HID + j];
            wb[b] = W2[(l + 32) * HID + j];
        }
        float2* tg = (float2*)(base + OFF_TBL4) + l;
        tg[0] = make_float2(0.f, 0.f);
        for (int n = 1; n < 16; n++) {
            int b = __ffs(n) - 1;
            float2 prev = tg[(n & (n - 1)) * 32];
            tg[n * 32] = make_float2(prev.x + wa[b], prev.y + wb[b]);
        }
    }
    // ---- stage W1 transposed ----
    {
        float2* w1t = (float2*)(base + OFF_W1T);
        for (int idx = tid; idx < SEQ * 32; idx += 1024) {
            int k = idx >> 5, l = idx & 31;
            w1t[k * 32 + l] =
                make_float2(W1[l * SEQ + k], W1[(l + 32) * SEQ + k]);
        }
    }
    __syncthreads();

    // per-lane constants
    const float b1_0 = b1[lane], b1_1 = b1[lane + 32];
    const float b2_0 = b2[lane], b2_1 = b2[lane + 32];
    const int   a3 = lane & 3;             // action owned by this lane
    const float b3me = b3[a3];
    const bool  lb0 = (lane & 1) != 0, lb1 = (lane & 2) != 0;
    const int w30q0 = __float2int_rn(W3[0 * HID + lane]      * W3_SCALE);
    const int w30q1 = __float2int_rn(W3[0 * HID + lane + 32] * W3_SCALE);
    const int w31q0 = __float2int_rn(W3[1 * HID + lane]      * W3_SCALE);
    const int w31q1 = __float2int_rn(W3[1 * HID + lane + 32] * W3_SCALE);
    const int w32q0 = __float2int_rn(W3[2 * HID + lane]      * W3_SCALE);
    const int w32q1 = __float2int_rn(W3[2 * HID + lane + 32] * W3_SCALE);
    const int w33q0 = __float2int_rn(W3[3 * HID + lane]      * W3_SCALE);
    const int w33q1 = __float2int_rn(W3[3 * HID + lane + 32] * W3_SCALE);

    const unsigned tb_lane = ab + (unsigned)lane * 8u;  // bits [13:8] = 0

    unsigned long long b2p;
    asm("mov.b64 %0, {%1, %2};" : "=l"(b2p) : "f"(b2_0), "f"(b2_1));

    const int lmod = lane & 15;
    const int lhi  = lane >> 4;

    // spike counters (register-resident; max 14 per nibble)
    unsigned c00 = 0u, c01 = 0u;   // neuron l: t 0-7, t 8-15
    unsigned c10 = 0u, c11 = 0u;   // neuron l+32
    unsigned cA = 0u, cB = 0u;     // s3 at (t=lmod, a=lhi) and (t=lmod, a=2+lhi)

    const int gwarp = blockIdx.x * WPB + warp;
    const int row0  = gwarp * 13 + min(gwarp, ROWS_EXTRA);
    const int nrows = 13 + (gwarp < ROWS_EXTRA ? 1 : 0);

    const float2* w1t = (const float2*)(base + OFF_W1T);

    for (int r = 0; r < nrows; r++) {
        const int row = row0 + r;

        // ---- cur1 = x[row] @ W1^T + b1 (coalesced + shfl broadcast) ----
        const float* xr = x + row * SEQ;
        float xown = (lane < SEQ) ? xr[lane] : 0.0f;
        float cur0 = b1_0, cur1v = b1_1;
        #pragma unroll
        for (int k = 0; k < SEQ; k++) {
            float xv = __shfl_sync(0xffffffffu, xown, k);
            float2 w = w1t[k * 32 + lane];
            cur0  = fmaf(xv, w.x, cur0);
            cur1v = fmaf(xv, w.y, cur1v);
        }

        float m1_0 = 0.f, m1_1 = 0.f, m2_0 = 0.f, m2_1 = 0.f;
        float m3me = 0.f, acme = 0.f;

        #pragma unroll
        for (int t = 0; t < TSTEP; t++) {
            // ---- layer 1 ----
            m1_0 = fmaf(BETA, m1_0, cur0);
            m1_1 = fmaf(BETA, m1_1, cur1v);
            bool f0 = m1_0 > THRV, f1 = m1_1 > THRV;
            if (f0) m1_0 -= THRV;
            if (f1) m1_1 -= THRV;
            unsigned ma = __ballot_sync(0xffffffffu, f0);  // neurons 0..31
            unsigned mb = __ballot_sync(0xffffffffu, f1);  // neurons 32..63

            // ---- layer 2: 11 LUT lookups (SHF + LOP3 + LDS + FADD2 each) ----
            unsigned long long a01 = b2p, aA = 0, aB = 0, aC = 0;
            lutW2<0 * 16384, 0x3F00u>(ma << 8,                      tb_lane, a01);
            lutW2<1 * 16384, 0x3F00u>(ma << 2,                      tb_lane, aA);
            lutW2<2 * 16384, 0x3F00u>(ma >> 4,                      tb_lane, aB);
            lutW2<3 * 16384, 0x3F00u>(ma >> 10,                     tb_lane, aC);
            lutW2<4 * 16384, 0x3F00u>(ma >> 16,                     tb_lane, a01);
            lutW2<5 * 16384, 0x3F00u>(__funnelshift_r(ma, mb, 22),  tb_lane, aA);
            lutW2<6 * 16384, 0x3F00u>(mb << 4,                      tb_lane, aB);
            lutW2<7 * 16384, 0x3F00u>(mb >> 2,                      tb_lane, aC);
            lutW2<8 * 16384, 0x3F00u>(mb >> 8,                      tb_lane, a01);
            lutW2<9 * 16384, 0x3F00u>(mb >> 14,                     tb_lane, aA);
            lutW2<OFF_TBL4,  0x0F00u>(mb >> 20,                     tb_lane, aB);
            asm("add.rn.f32x2 %0, %0, %1;" : "+l"(a01) : "l"(aA));
            asm("add.rn.f32x2 %0, %0, %1;" : "+l"(aB)  : "l"(aC));
            asm("add.rn.f32x2 %0, %0, %1;" : "+l"(a01) : "l"(aB));
            float a0, a1;
            asm("mov.b64 {%0, %1}, %2;" : "=f"(a0), "=f"(a1) : "l"(a01));

            m2_0 = fmaf(BETA, m2_0, a0);
            m2_1 = fmaf(BETA, m2_1, a1);
            bool q0 = m2_0 > THRV, q1 = m2_1 > THRV;
            if (q0) m2_0 -= THRV;
            if (q1) m2_1 -= THRV;

            // s2 nibble counters (t immediate under full unroll)
            unsigned nib = 1u << ((t & 7) * 4);
            if (t < 8) { c00 += q0 ? nib : 0u; c10 += q1 ? nib : 0u; }
            else       { c01 += q0 ? nib : 0u; c11 += q1 ? nib : 0u; }

            // ---- layer 3: exact integer IMAD partials + 4 warp reduxes ----
            int s0i = q0 ? 1 : 0, s1i = q1 ? 1 : 0;
            int p0i = s0i * w30q0 + s1i * w30q1;
            int p1i = s0i * w31q0 + s1i * w31q1;
            int p2i = s0i * w32q0 + s1i * w32q1;
            int p3i = s0i * w33q0 + s1i * w33q1;
            p0i = warp_redux_add_s32(p0i);
            p1i = warp_redux_add_s32(p1i);
            p2i = warp_redux_add_s32(p2i);
            p3i = warp_redux_add_s32(p3i);

            // this lane updates only its own action
            int pm = lb1 ? (lb0 ? p3i : p2i) : (lb0 ? p1i : p0i);
            float pf = fmaf((float)pm, W3_INV_SCALE, b3me);
            m3me = fmaf(BETA, m3me, pf);
            bool gme = m3me > THRV;
            if (gme) { m3me -= THRV; acme += 1.0f; }

            unsigned bal = __ballot_sync(0xffffffffu, gme);   // bits repeat mod 4
            if (lmod == t) {
                cA += (bal >> lhi) & 1u;
                cB += (bal >> (2 + lhi)) & 1u;
            }
        }

        // ---- softmax(acc / T): gather 4 actions, lane 0 writes ----
        float gg0 = __shfl_sync(0xffffffffu, acme, 0);
        float gg1 = __shfl_sync(0xffffffffu, acme, 1);
        float gg2 = __shfl_sync(0xffffffffu, acme, 2);
        float gg3 = __shfl_sync(0xffffffffu, acme, 3);
        if (lane == 0) {
            const float invT = 1.0f / (float)TSTEP;
            float r0 = gg0 * invT, r1 = gg1 * invT;
            float r2 = gg2 * invT, r3 = gg3 * invT;
            float mx = fmaxf(fmaxf(r0, r1), fmaxf(r2, r3));
            float e0 = __expf(r0 - mx), e1 = __expf(r1 - mx);
            float e2 = __expf(r2 - mx), e3 = __expf(r3 - mx);
            float rs = __fdividef(1.0f, e0 + e1 + e2 + e3);
            float4 o = make_float4(e0 * rs, e1 * rs, e2 * rs, e3 * rs);
            *reinterpret_cast<float4*>(out + (size_t)row * ACT) = o;
        }
    }

    // ---- flush spike counters (alias counter buffers onto tbl6 region) ----
    __syncthreads();                       // all warps done with the LUTs
    unsigned (*s2sh)[32][4] = (unsigned(*)[32][4])(base);          // 16KB
    unsigned (*s3sh)[32][2] = (unsigned(*)[32][2])(base + 16384);  //  8KB
    s2sh[warp][lane][0] = c00;
    s2sh[warp][lane][1] = c01;
    s2sh[warp][lane][2] = c10;
    s2sh[warp][lane][3] = c11;
    s3sh[warp][lane][0] = cA;
    s3sh[warp][lane][1] = cB;
    __syncthreads();

    {   // 1024 (t, neuron) cells, one per thread
        int p = tid;
        int t = p >> 6, j = p & 63;
        int ln = j & 31, half = j >> 5;
        int wsel = half * 2 + (t >> 3);
        int sh = (t & 7) * 4;
        unsigned c = 0;
        #pragma unroll
        for (int w = 0; w < WPB; w++)
            c += (s2sh[w][ln][wsel] >> sh) & 15u;
        atomicAdd(&g_s2sum[p], (float)c);
    }
    if (tid < TSTEP * ACT) {
        int t = tid >> 2, a = tid & 3;
        int ln = t + ((a & 1) << 4);
        int s = a >> 1;
        unsigned c = 0;
        #pragma unroll
        for (int w = 0; w < WPB; w++)
            c += s3sh[w][ln][s];
        atomicAdd(&g_s3sum[tid], (float)c);
    }

    // ---- last-block: eligibility trace + reset of globals ----
    unsigned* flagp = (unsigned*)(base + OFF_FLAG);
    __threadfence();
    __syncthreads();
    if (tid == 0)
        *flagp = (atomicAdd(&g_ctr, 1u) == (unsigned)(NBLK - 1)) ? 1u : 0u;
    __syncthreads();
    if (*flagp) {
        if (tid < ACT * HID) {
            int a = tid >> 6, h = tid & 63;
            const float invB = 1.0f / (float)BSZ;
            volatile float* s3v = g_s3sum;
            volatile float* s2v = g_s2sum;
            float e = elig0[tid];
            #pragma unroll
            for (int t = 0; t < TSTEP; t++) {
                float post = s3v[t * ACT + a] * invB;
                float pre  = s2v[t * HID + h] * invB;
                e = ELIG_DECAY * e + ELIG_C * (post * pre);
            }
            out[elig_off + tid] = e;
        }
        __syncthreads();
        if (tid < TSTEP * HID) g_s2sum[tid] = 0.0f;
        if (tid < TSTEP * ACT) g_s3sum[tid] = 0.0f;
        if (tid == 0) g_ctr = 0u;
    }
}

// ---------------------------------------------------------------------------
// Inputs (metadata order): x, W1, b1, W2, b2, W3, b3, elig0
// Output: probs [B,4] then elig [4,64] at the tail of out.
// ---------------------------------------------------------------------------
extern "C" void kernel_launch(void* const* d_in, const int* in_sizes, int n_in,
                              void* d_out, int out_size) {
    const float* x     = (const float*)d_in[0];
    const float* W1    = (const float*)d_in[1];
    const float* b1    = (const float*)d_in[2];
    const float* W2    = (const float*)d_in[3];
    const float* b2    = (const float*)d_in[4];
    const float* W3    = (const float*)d_in[5];
    const float* b3    = (const float*)d_in[6];
    const float* elig0 = (const float*)d_in[7];
    float* out = (float*)d_out;

    cudaFuncSetAttribute(snn_main, cudaFuncAttributeMaxDynamicSharedMemorySize,
                         SMEM_REQ);
    int elig_off = out_size - ACT * HID;
    snn_main<<<NBLK, 1024, SMEM_REQ>>>(x, W1, b1, W2, b2, W3, b3,
                                       elig0, out, elig_off);
}

// round 11
// speedup vs baseline: 1.1747x; 1.0196x over previous
#include <cuda_runtime.h>
#include <math.h>

#define BSZ   65536
#define SEQ   25
#define HID   64
#define ACT   4
#define TSTEP 16
#define BETA  0.95f
#define THRV  1.0f
#define ELIG_DECAY 0.95f
#define ELIG_C     (-0.002f)    // A_PLUS - A_MINUS

#define NBLK  148               // 1 block per SM, single wave
#define WPB   32                // warps per block (1024 threads)
// 65536 = 4736*13 + 3968 -> first 3968 warps take 14 rows (<= nibble cap 15)
#define ROWS_EXTRA 3968

#define W3_SCALE     8388608.0f          // 2^23 (exact integer reduction)
#define W3_INV_SCALE (1.0f / 8388608.0f)

// ---- aligned-region byte offsets (from 16KB-aligned base "ab") ----
// tbl6 : 10 groups x 64 pat x 32 lanes x float2 = 163840 (group g at g*16384)
// tbl4 : 16 pat x 32 lanes x float2             =   4096 (at 163840, 16K-aligned)
// w1t  : 25 x 32 x float2                       =   6400 (at 167936)
// flag : 4                                        (at 174336)
// s2sh (16KB) / s3sh (1KB) alias tbl6 region after the main loop.
#define OFF_TBL4  163840
#define OFF_W1T   167936
#define OFF_FLAG  174336
#define SMEM_REQ  (174464 + 16384)   // payload + alignment slack

// Graph-safe persistent scratch; last block re-zeroes everything each call.
__device__ float    g_s2sum[TSTEP * HID];
__device__ float    g_s3sum[TSTEP * ACT];
__device__ unsigned g_ctr;

__device__ __forceinline__ int warp_redux_add_s32(int v) {
    int r;
    asm volatile("redux.sync.add.s32 %0, %1, 0xffffffff;" : "=r"(r) : "r"(v));
    return r;
}

// W2 LUT lookup: v has the pattern pre-shifted to bits [8,14).
// addr = (v & MASK) | tb_lane  (single LOP3, valid because tb_lane bits[13:8]=0)
template <int IMM, unsigned MASK>
__device__ __forceinline__ void lutW2(unsigned v, unsigned tb_lane,
                                      unsigned long long& acc) {
    unsigned addr;
    asm("lop3.b32 %0, %1, %2, %3, 0xEA;"
        : "=r"(addr) : "r"(v), "n"(MASK), "r"(tb_lane));
    unsigned long long w;
    asm volatile("ld.shared.b64 %0, [%1+%2];" : "=l"(w) : "r"(addr), "n"(IMM));
    asm("add.rn.f32x2 %0, %0, %1;" : "+l"(acc) : "l"(w));
}

// ---------------------------------------------------------------------------
// Fused kernel. One warp per batch row (13-14 rows/warp).
// Lane l owns hidden neurons l and l+32 (layers 1, 2).
// Layer 3: exact integer IMAD partials (FMA pipe) + 4 warp reduxes;
// lane l keeps m3/acc AND per-t spike counts for action lane&3 (no s3 ballot).
// ---------------------------------------------------------------------------
__global__ void __launch_bounds__(1024, 1) snn_main(
    const float* __restrict__ x,   // [B, 25]
    const float* __restrict__ W1,  // [64, 25]
    const float* __restrict__ b1,  // [64]
    const float* __restrict__ W2,  // [64, 64]
    const float* __restrict__ b2,  // [64]
    const float* __restrict__ W3,  // [4, 64]
    const float* __restrict__ b3,  // [4]
    const float* __restrict__ elig0,
    float* __restrict__ out, int elig_off)
{
    extern __shared__ unsigned char smem_raw[];
    const unsigned dyn = (unsigned)__cvta_generic_to_shared(smem_raw);
    const unsigned ab  = (dyn + 16383u) & 0xFFFFC000u;   // 16KB-aligned base
    unsigned char* base = smem_raw + (ab - dyn);

    const int tid  = threadIdx.x;
    const int lane = tid & 31;
    const int warp = tid >> 5;

    // ---- build 6-bit W2 LUT (tbl6[g][pat][lane] = float2 partial col sums) ----
    if (tid < 320) {
        const int g = tid >> 5, l = tid & 31;
        float wa[6], wb[6];
        #pragma unroll
        for (int b = 0; b < 6; b++) {
            int j = 6 * g + b;
            wa[b] = W2[l * HID + j];
            wb[b] = W2[(l + 32) * HID + j];
        }
        float2* tg = (float2*)(base + g * 16384) + l;     // stride 32 float2
        tg[0] = make_float2(0.f, 0.f);
        for (int n = 1; n < 64; n++) {
            int b = __ffs(n) - 1;
            float2 prev = tg[(n & (n - 1)) * 32];
            tg[n * 32] = make_float2(prev.x + wa[b], prev.y + wb[b]);
        }
    } else if (tid < 352) {
        const int l = tid - 320;
        float wa[4], wb[4];
        #pragma unroll
        for (int b = 0; b < 4; b++) {
            int j = 60 + b;
            wa[b] = W2[l * HID + j];
            wb[b] = W2[(l + 32) * HID + j];
        }
        float2* tg = (float2*)(base + OFF_TBL4) + l;
        tg[0] = make_float2(0.f, 0.f);
        for (int n = 1; n < 16; n++) {
            int b = __ffs(n) - 1;
            float2 prev = tg[(n & (n - 1)) * 32];
            tg[n * 32] = make_float2(prev.x + wa[b], prev.y + wb[b]);
        }
    }
    // ---- stage W1 transposed ----
    {
        float2* w1t = (float2*)(base + OFF_W1T);
        for (int idx = tid; idx < SEQ * 32; idx += 1024) {
            int k = idx >> 5, l = idx & 31;
            w1t[k * 32 + l] =
                make_float2(W1[l * SEQ + k], W1[(l + 32) * SEQ + k]);
        }
    }
    __syncthreads();

    // per-lane constants
    const float b1_0 = b1[lane], b1_1 = b1[lane + 32];
    const float b2_0 = b2[lane], b2_1 = b2[lane + 32];
    const int   a3 = lane & 3;             // action owned by this lane
    const float b3me = b3[a3];
    const bool  lb0 = (lane & 1) != 0, lb1 = (lane & 2) != 0;
    const int w30q0 = __float2int_rn(W3[0 * HID + lane]      * W3_SCALE);
    const int w30q1 = __float2int_rn(W3[0 * HID + lane + 32] * W3_SCALE);
    const int w31q0 = __float2int_rn(W3[1 * HID + lane]      * W3_SCALE);
    const int w31q1 = __float2int_rn(W3[1 * HID + lane + 32] * W3_SCALE);
    const int w32q0 = __float2int_rn(W3[2 * HID + lane]      * W3_SCALE);
    const int w32q1 = __float2int_rn(W3[2 * HID + lane + 32] * W3_SCALE);
    const int w33q0 = __float2int_rn(W3[3 * HID + lane]      * W3_SCALE);
    const int w33q1 = __float2int_rn(W3[3 * HID + lane + 32] * W3_SCALE);

    const unsigned tb_lane = ab + (unsigned)lane * 8u;  // bits [13:8] = 0

    unsigned long long b2p;
    asm("mov.b64 %0, {%1, %2};" : "=l"(b2p) : "f"(b2_0), "f"(b2_1));

    // spike counters (register-resident; max 14 per nibble)
    unsigned c00 = 0u, c01 = 0u;   // s2 neuron l: t 0-7, t 8-15
    unsigned c10 = 0u, c11 = 0u;   // s2 neuron l+32
    unsigned cme_lo = 0u, cme_hi = 0u;  // s3 counts for action a3, per-t nibbles

    const int gwarp = blockIdx.x * WPB + warp;
    const int row0  = gwarp * 13 + min(gwarp, ROWS_EXTRA);
    const int nrows = 13 + (gwarp < ROWS_EXTRA ? 1 : 0);

    const float2* w1t = (const float2*)(base + OFF_W1T);

    for (int r = 0; r < nrows; r++) {
        const int row = row0 + r;

        // ---- cur1 = x[row] @ W1^T + b1 (coalesced + shfl broadcast) ----
        const float* xr = x + row * SEQ;
        float xown = (lane < SEQ) ? xr[lane] : 0.0f;
        float cur0 = b1_0, cur1v = b1_1;
        #pragma unroll
        for (int k = 0; k < SEQ; k++) {
            float xv = __shfl_sync(0xffffffffu, xown, k);
            float2 w = w1t[k * 32 + lane];
            cur0  = fmaf(xv, w.x, cur0);
            cur1v = fmaf(xv, w.y, cur1v);
        }

        float m1_0 = 0.f, m1_1 = 0.f, m2_0 = 0.f, m2_1 = 0.f;
        float m3me = 0.f, acme = 0.f;

        #pragma unroll
        for (int t = 0; t < TSTEP; t++) {
            // ---- layer 1 ----
            m1_0 = fmaf(BETA, m1_0, cur0);
            m1_1 = fmaf(BETA, m1_1, cur1v);
            bool f0 = m1_0 > THRV, f1 = m1_1 > THRV;
            if (f0) m1_0 -= THRV;
            if (f1) m1_1 -= THRV;
            unsigned ma = __ballot_sync(0xffffffffu, f0);  // neurons 0..31
            unsigned mb = __ballot_sync(0xffffffffu, f1);  // neurons 32..63

            // ---- layer 2: 11 LUT lookups (SHF + LOP3 + LDS + FADD2 each) ----
            unsigned long long a01 = b2p, aA = 0, aB = 0, aC = 0;
            lutW2<0 * 16384, 0x3F00u>(ma << 8,                      tb_lane, a01);
            lutW2<1 * 16384, 0x3F00u>(ma << 2,                      tb_lane, aA);
            lutW2<2 * 16384, 0x3F00u>(ma >> 4,                      tb_lane, aB);
            lutW2<3 * 16384, 0x3F00u>(ma >> 10,                     tb_lane, aC);
            lutW2<4 * 16384, 0x3F00u>(ma >> 16,                     tb_lane, a01);
            lutW2<5 * 16384, 0x3F00u>(__funnelshift_r(ma, mb, 22),  tb_lane, aA);
            lutW2<6 * 16384, 0x3F00u>(mb << 4,                      tb_lane, aB);
            lutW2<7 * 16384, 0x3F00u>(mb >> 2,                      tb_lane, aC);
            lutW2<8 * 16384, 0x3F00u>(mb >> 8,                      tb_lane, a01);
            lutW2<9 * 16384, 0x3F00u>(mb >> 14,                     tb_lane, aA);
            lutW2<OFF_TBL4,  0x0F00u>(mb >> 20,                     tb_lane, aB);
            asm("add.rn.f32x2 %0, %0, %1;" : "+l"(a01) : "l"(aA));
            asm("add.rn.f32x2 %0, %0, %1;" : "+l"(aB)  : "l"(aC));
            asm("add.rn.f32x2 %0, %0, %1;" : "+l"(a01) : "l"(aB));
            float a0, a1;
            asm("mov.b64 {%0, %1}, %2;" : "=f"(a0), "=f"(a1) : "l"(a01));

            m2_0 = fmaf(BETA, m2_0, a0);
            m2_1 = fmaf(BETA, m2_1, a1);
            bool q0 = m2_0 > THRV, q1 = m2_1 > THRV;
            if (q0) m2_0 -= THRV;
            if (q1) m2_1 -= THRV;

            // s2 nibble counters (t immediate under full unroll)
            unsigned nib = 1u << ((t & 7) * 4);
            if (t < 8) { c00 += q0 ? nib : 0u; c10 += q1 ? nib : 0u; }
            else       { c01 += q0 ? nib : 0u; c11 += q1 ? nib : 0u; }

            // ---- layer 3: exact integer IMAD partials + 4 warp reduxes ----
            int s0i = q0 ? 1 : 0, s1i = q1 ? 1 : 0;
            int p0i = s0i * w30q0 + s1i * w30q1;
            int p1i = s0i * w31q0 + s1i * w31q1;
            int p2i = s0i * w32q0 + s1i * w32q1;
            int p3i = s0i * w33q0 + s1i * w33q1;
            p0i = warp_redux_add_s32(p0i);
            p1i = warp_redux_add_s32(p1i);
            p2i = warp_redux_add_s32(p2i);
            p3i = warp_redux_add_s32(p3i);

            // this lane updates only its own action (no ballot, no sync)
            int pm = lb1 ? (lb0 ? p3i : p2i) : (lb0 ? p1i : p0i);
            float pf = fmaf((float)pm, W3_INV_SCALE, b3me);
            m3me = fmaf(BETA, m3me, pf);
            bool gme = m3me > THRV;
            if (gme) { m3me -= THRV; acme += 1.0f; }

            // s3 per-t nibble counters for this lane's action
            if (t < 8) { cme_lo += gme ? nib : 0u; }
            else       { cme_hi += gme ? nib : 0u; }
        }

        // ---- softmax(acc / T): gather 4 actions, lane 0 writes ----
        float gg0 = __shfl_sync(0xffffffffu, acme, 0);
        float gg1 = __shfl_sync(0xffffffffu, acme, 1);
        float gg2 = __shfl_sync(0xffffffffu, acme, 2);
        float gg3 = __shfl_sync(0xffffffffu, acme, 3);
        if (lane == 0) {
            const float invT = 1.0f / (float)TSTEP;
            float r0 = gg0 * invT, r1 = gg1 * invT;
            float r2 = gg2 * invT, r3 = gg3 * invT;
            float mx = fmaxf(fmaxf(r0, r1), fmaxf(r2, r3));
            float e0 = __expf(r0 - mx), e1 = __expf(r1 - mx);
            float e2 = __expf(r2 - mx), e3 = __expf(r3 - mx);
            float rs = __fdividef(1.0f, e0 + e1 + e2 + e3);
            float4 o = make_float4(e0 * rs, e1 * rs, e2 * rs, e3 * rs);
            *reinterpret_cast<float4*>(out + (size_t)row * ACT) = o;
        }
    }

    // ---- flush spike counters (alias counter buffers onto tbl6 region) ----
    __syncthreads();                       // all warps done with the LUTs
    unsigned (*s2sh)[32][4] = (unsigned(*)[32][4])(base);          // 16KB
    unsigned (*s3sh)[8]     = (unsigned(*)[8])(base + 16384);      //  1KB
    s2sh[warp][lane][0] = c00;
    s2sh[warp][lane][1] = c01;
    s2sh[warp][lane][2] = c10;
    s2sh[warp][lane][3] = c11;
    if (lane < 4) {                        // dedupe: lanes 0-3 = actions 0-3
        s3sh[warp][lane * 2 + 0] = cme_lo;
        s3sh[warp][lane * 2 + 1] = cme_hi;
    }
    __syncthreads();

    {   // 1024 (t, neuron) s2 cells, one per thread
        int p = tid;
        int t = p >> 6, j = p & 63;
        int ln = j & 31, half = j >> 5;
        int wsel = half * 2 + (t >> 3);
        int sh = (t & 7) * 4;
        unsigned c = 0;
        #pragma unroll
        for (int w = 0; w < WPB; w++)
            c += (s2sh[w][ln][wsel] >> sh) & 15u;
        atomicAdd(&g_s2sum[p], (float)c);
    }
    if (tid < TSTEP * ACT) {               // 64 (t, action) s3 cells
        int t = tid >> 2, a = tid & 3;
        int slot = a * 2 + (t >> 3);
        int sh = (t & 7) * 4;
        unsigned c = 0;
        #pragma unroll
        for (int w = 0; w < WPB; w++)
            c += (s3sh[w][slot] >> sh) & 15u;
        atomicAdd(&g_s3sum[tid], (float)c);
    }

    // ---- last-block: eligibility trace + reset of globals ----
    unsigned* flagp = (unsigned*)(base + OFF_FLAG);
    __threadfence();
    __syncthreads();
    if (tid == 0)
        *flagp = (atomicAdd(&g_ctr, 1u) == (unsigned)(NBLK - 1)) ? 1u : 0u;
    __syncthreads();
    if (*flagp) {
        if (tid < ACT * HID) {
            int a = tid >> 6, h = tid & 63;
            const float invB = 1.0f / (float)BSZ;
            volatile float* s3v = g_s3sum;
            volatile float* s2v = g_s2sum;
            float e = elig0[tid];
            #pragma unroll
            for (int t = 0; t < TSTEP; t++) {
                float post = s3v[t * ACT + a] * invB;
                float pre  = s2v[t * HID + h] * invB;
                e = ELIG_DECAY * e + ELIG_C * (post * pre);
            }
            out[elig_off + tid] = e;
        }
        __syncthreads();
        if (tid < TSTEP * HID) g_s2sum[tid] = 0.0f;
        if (tid < TSTEP * ACT) g_s3sum[tid] = 0.0f;
        if (tid == 0) g_ctr = 0u;
    }
}

// ---------------------------------------------------------------------------
// Inputs (metadata order): x, W1, b1, W2, b2, W3, b3, elig0
// Output: probs [B,4] then elig [4,64] at the tail of out.
// ---------------------------------------------------------------------------
extern "C" void kernel_launch(void* const* d_in, const int* in_sizes, int n_in,
                              void* d_out, int out_size) {
    const float* x     = (const float*)d_in[0];
    const float* W1    = (const float*)d_in[1];
    const float* b1    = (const float*)d_in[2];
    const float* W2    = (const float*)d_in[3];
    const float* b2    = (const float*)d_in[4];
    const float* W3    = (const float*)d_in[5];
    const float* b3    = (const float*)d_in[6];
    const float* elig0 = (const float*)d_in[7];
    float* out = (float*)d_out;

    cudaFuncSetAttribute(snn_main, cudaFuncAttributeMaxDynamicSharedMemorySize,
                         SMEM_REQ);
    int elig_off = out_size - ACT * HID;
    snn_main<<<NBLK, 1024, SMEM_REQ>>>(x, W1, b1, W2, b2, W3, b3,
                                       elig0, out, elig_off);
}